// round 11
// baseline (speedup 1.0000x reference)
#include <cuda_runtime.h>
#include <cuda_fp16.h>

#define NNODES 200000
#define AF 82
#define H 10
#define ED 6
#define STRIDE 12     // fp32 h rows: 48B
#define PSTRIDE 16    // fp16 p rows: 32B (halves 10..15 permanent zeros)
#define NPLANES 4
#define APSTRIDE 16   // fp16 agg plane rows: 32B
#define EPB 128       // edges per block (256 threads, 2 lanes/edge)

__device__ float g_h[(size_t)NNODES * STRIDE];
__device__ __half g_p[(size_t)NNODES * PSTRIDE];
__device__ __half g_aggh[(size_t)NPLANES * NNODES * APSTRIDE];   // 25.6MB

__device__ __forceinline__ float lrelu(float x) { return fmaxf(x, 0.1f * x); }

__device__ __forceinline__ void store_p_fp16(__half* pr, const float* pv) {
    __half2 t0 = __floats2half2_rn(pv[0], pv[1]);
    __half2 t1 = __floats2half2_rn(pv[2], pv[3]);
    __half2 t2 = __floats2half2_rn(pv[4], pv[5]);
    __half2 t3 = __floats2half2_rn(pv[6], pv[7]);
    __half2 t4 = __floats2half2_rn(pv[8], pv[9]);
    uint4 q;
    q.x = *(unsigned*)&t0; q.y = *(unsigned*)&t1;
    q.z = *(unsigned*)&t2; q.w = *(unsigned*)&t3;
    *(uint4*)pr = q;
    uint4 q2;
    q2.x = *(unsigned*)&t4; q2.y = 0u; q2.z = 0u; q2.w = 0u;
    *(uint4*)(pr + 8) = q2;
}

__device__ __forceinline__ void zero_planes(int node) {
    uint4 z = make_uint4(0, 0, 0, 0);
#pragma unroll
    for (int pl = 0; pl < NPLANES; pl++) {
        __half* ar = g_aggh + ((size_t)pl * NNODES + node) * APSTRIDE;
        ((uint4*)ar)[0] = z;
        ((uint4*)ar)[1] = z;
    }
}

// ---------------------------------------------------------------------------
// init: h = lrelu(vertex @ Wi); p = h @ Wg_top; zero agg planes (layer-0 prep)
// ---------------------------------------------------------------------------
__global__ void init_kernel(const float* __restrict__ vertex,
                            const float* __restrict__ Wi,
                            const float* __restrict__ Wg, int n) {
    __shared__ float wi[AF * H];
    __shared__ float wg[H * H];
    for (int i = threadIdx.x; i < AF * H; i += blockDim.x) wi[i] = Wi[i];
    for (int i = threadIdx.x; i < H * H; i += blockDim.x) wg[i] = Wg[i];
    __syncthreads();
    int node = blockIdx.x * blockDim.x + threadIdx.x;
    if (node >= n) return;

    zero_planes(node);

    const float* row = vertex + (size_t)node * AF;
    float acc[H];
#pragma unroll
    for (int j = 0; j < H; j++) acc[j] = 0.f;

    int base = (node & 1) ? 2 : 0;
    if (node & 1) {
        float2 hd = *(const float2*)row;
#pragma unroll
        for (int j = 0; j < H; j++)
            acc[j] += hd.x * wi[0 * H + j] + hd.y * wi[1 * H + j];
    }
    const float4* r4 = (const float4*)(row + base);
    const float* wb = wi + base * H;
#pragma unroll
    for (int i = 0; i < 20; i++) {
        float4 v = r4[i];
        const float* wk = wb + (4 * i) * H;
#pragma unroll
        for (int j = 0; j < H; j++)
            acc[j] += v.x * wk[j] + v.y * wk[H + j] +
                      v.z * wk[2 * H + j] + v.w * wk[3 * H + j];
    }
    if (!(node & 1)) {
        float2 tl = *(const float2*)(row + 80);
#pragma unroll
        for (int j = 0; j < H; j++)
            acc[j] += tl.x * wi[80 * H + j] + tl.y * wi[81 * H + j];
    }

    float h[H];
#pragma unroll
    for (int j = 0; j < H; j++) h[j] = lrelu(acc[j]);

    float pv[H];
#pragma unroll
    for (int j = 0; j < H; j++) {
        float a = 0.f;
#pragma unroll
        for (int i = 0; i < H; i++) a += h[i] * wg[i * H + j];
        pv[j] = a;
    }

    float4* hw = (float4*)(g_h + (size_t)node * STRIDE);
    hw[0] = make_float4(h[0], h[1], h[2], h[3]);
    hw[1] = make_float4(h[4], h[5], h[6], h[7]);
    hw[2] = make_float4(h[8], h[9], 0.f, 0.f);
    store_p_fp16(g_p + (size_t)node * PSTRIDE, pv);
}

// ---------------------------------------------------------------------------
// edge: 2 lanes/edge; ef staged through shared memory with coalesced float4
// loads. Each lane: one LDG.128 p-gather (16B half-row), 8 output dims, one
// red.v4.f16x2 into its 16B half of the agg row (plane = e&3).
// ---------------------------------------------------------------------------
__global__ void __launch_bounds__(256, 8)
edge_kernel(const float* __restrict__ ef,
            const int* __restrict__ src,
            const int* __restrict__ dst,
            const float* __restrict__ Wg, int ecnt) {
    __shared__ float wpad[ED][16];
    __shared__ float s_ef[EPB * ED];   // 3KB: this block's 128 edge rows
    for (int i = threadIdx.x; i < ED * 16; i += blockDim.x) {
        int k = i >> 4, j = i & 15;
        wpad[k][j] = (j < H) ? Wg[(H + k) * H + j] : 0.f;
    }

    int eb0 = blockIdx.x * EPB;                 // first edge of this block
    // stage ef: 128 edges * 6 floats = 192 float4 loads, fully coalesced
    {
        long long fbase = (long long)eb0 * ED;  // first float index
        long long ftot = (long long)ecnt * ED;
        int t = threadIdx.x;
        if (t < EPB * ED / 4) {
            long long gf = fbase + (long long)t * 4;
            if (gf + 4 <= ftot) {
                *(float4*)&s_ef[t * 4] = *(const float4*)&ef[gf];
            } else {
#pragma unroll
                for (int k = 0; k < 4; k++)
                    s_ef[t * 4 + k] = (gf + k < ftot) ? ef[gf + k] : 0.f;
            }
        }
    }
    __syncthreads();

    int tid = blockIdx.x * blockDim.x + threadIdx.x;
    int e = tid >> 1;
    int role = tid & 1;
    if (e >= ecnt) return;

    int s = src[e];
    int d = dst[e];

    int le = e - eb0;
    const float2* ep = (const float2*)&s_ef[le * ED];
    float2 f0 = ep[0], f1 = ep[1], f2 = ep[2];
    float ev[ED] = {f0.x, f0.y, f1.x, f1.y, f2.x, f2.y};

    const __half* pr = g_p + (size_t)s * PSTRIDE + role * 8;
    uint4 q = *(const uint4*)pr;
    float pl[8];
    {
        float2 f;
        f = __half22float2(*(__half2*)&q.x); pl[0] = f.x; pl[1] = f.y;
        f = __half22float2(*(__half2*)&q.y); pl[2] = f.x; pl[3] = f.y;
        f = __half22float2(*(__half2*)&q.z); pl[4] = f.x; pl[5] = f.y;
        f = __half22float2(*(__half2*)&q.w); pl[6] = f.x; pl[7] = f.y;
    }

    const float* wj = &wpad[0][role * 8];
    float m[8];
#pragma unroll
    for (int jj = 0; jj < 8; jj++) {
        float a = pl[jj];
#pragma unroll
        for (int k = 0; k < ED; k++) a += ev[k] * wj[k * 16 + jj];
        m[jj] = lrelu(a);
    }

    __half2 h0 = __floats2half2_rn(m[0], m[1]);
    __half2 h1 = __floats2half2_rn(m[2], m[3]);
    __half2 h2 = __floats2half2_rn(m[4], m[5]);
    __half2 h3 = __floats2half2_rn(m[6], m[7]);

    int plane = e & (NPLANES - 1);
    __half* ap = g_aggh + ((size_t)plane * NNODES + d) * APSTRIDE + role * 8;
    asm volatile("red.global.add.noftz.v4.f16x2 [%0], {%1,%2,%3,%4};" ::
                 "l"(ap), "r"(*(unsigned*)&h0), "r"(*(unsigned*)&h1),
                 "r"(*(unsigned*)&h2), "r"(*(unsigned*)&h3) : "memory");
}

// ---------------------------------------------------------------------------
// update: agg = sum of 4 fp16 planes; h' = lrelu([h,agg] @ Wu);
// layer 0: also write p' and re-zero planes for next layer
// ---------------------------------------------------------------------------
__global__ void update_kernel(const float* __restrict__ Wu,
                              const float* __restrict__ Wg,
                              float* __restrict__ out, int n,
                              int out_stride, int write_p) {
    __shared__ float wu[2 * H * H];
    __shared__ float wg[H * H];
    for (int i = threadIdx.x; i < 2 * H * H; i += blockDim.x) wu[i] = Wu[i];
    for (int i = threadIdx.x; i < H * H; i += blockDim.x) wg[i] = Wg[i];
    __syncthreads();

    int node = blockIdx.x * blockDim.x + threadIdx.x;
    if (node >= n) return;

    size_t off = (size_t)node * STRIDE;
    const float4* hr = (const float4*)(g_h + off);
    float4 h0 = hr[0], h1 = hr[1], h2 = hr[2];
    float hv[H] = {h0.x, h0.y, h0.z, h0.w, h1.x, h1.y, h1.z, h1.w, h2.x, h2.y};

    float av[H];
#pragma unroll
    for (int j = 0; j < H; j++) av[j] = 0.f;
#pragma unroll
    for (int pl = 0; pl < NPLANES; pl++) {
        const __half* ar = g_aggh + ((size_t)pl * NNODES + node) * APSTRIDE;
        uint4 q = *(const uint4*)ar;
        unsigned t = *(const unsigned*)(ar + 8);
        float2 f;
        f = __half22float2(*(__half2*)&q.x); av[0] += f.x; av[1] += f.y;
        f = __half22float2(*(__half2*)&q.y); av[2] += f.x; av[3] += f.y;
        f = __half22float2(*(__half2*)&q.z); av[4] += f.x; av[5] += f.y;
        f = __half22float2(*(__half2*)&q.w); av[6] += f.x; av[7] += f.y;
        f = __half22float2(*(__half2*)&t);   av[8] += f.x; av[9] += f.y;
    }

    if (write_p) zero_planes(node);   // prep planes for next layer

    float o[H];
#pragma unroll
    for (int j = 0; j < H; j++) {
        float a = 0.f;
#pragma unroll
        for (int i = 0; i < H; i++) a += hv[i] * wu[i * H + j];
#pragma unroll
        for (int i = 0; i < H; i++) a += av[i] * wu[(H + i) * H + j];
        o[j] = lrelu(a);
    }

    if (out_stride == STRIDE) {
        float4* ow = (float4*)(out + (size_t)node * STRIDE);
        ow[0] = make_float4(o[0], o[1], o[2], o[3]);
        ow[1] = make_float4(o[4], o[5], o[6], o[7]);
        ow[2] = make_float4(o[8], o[9], 0.f, 0.f);
    } else {
        float2* ow = (float2*)(out + (size_t)node * H);
#pragma unroll
        for (int j = 0; j < H / 2; j++) ow[j] = make_float2(o[2 * j], o[2 * j + 1]);
    }

    if (write_p) {
        float pv[H];
#pragma unroll
        for (int j = 0; j < H; j++) {
            float a = 0.f;
#pragma unroll
            for (int i = 0; i < H; i++) a += o[i] * wg[i * H + j];
            pv[j] = a;
        }
        store_p_fp16(g_p + (size_t)node * PSTRIDE, pv);
    }
}

// ---------------------------------------------------------------------------
extern "C" void kernel_launch(void* const* d_in, const int* in_sizes, int n_in,
                              void* d_out, int out_size) {
    const float* vertex = (const float*)d_in[0];
    const float* ef = (const float*)d_in[1];
    const int* src = (const int*)d_in[2];
    const int* dst = (const int*)d_in[3];
    const float* Wi = (const float*)d_in[4];
    const float* Wg = (const float*)d_in[5];
    const float* Wu = (const float*)d_in[6];
    float* out = (float*)d_out;

    int n = in_sizes[0] / AF;
    int e = in_sizes[2];

    void* hp = nullptr;
    cudaGetSymbolAddress(&hp, g_h);

    int nb = (n + 255) / 256;
    int eb = (e + EPB - 1) / EPB;

    init_kernel<<<nb, 256>>>(vertex, Wi, Wg, n);
    for (int l = 0; l < 2; l++) {
        edge_kernel<<<eb, 256>>>(ef, src, dst, Wg, e);
        update_kernel<<<nb, 256>>>(Wu, Wg, (l == 1) ? out : (float*)hp, n,
                                   (l == 1) ? H : STRIDE, (l == 0) ? 1 : 0);
    }
}

// round 13
// speedup vs baseline: 1.2338x; 1.2338x over previous
#include <cuda_runtime.h>
#include <cuda_fp16.h>

#define NNODES 200000
#define AF 82
#define H 10
#define ED 6
#define STRIDE 12     // fp32 h rows: 48B
#define PSTRIDE 16    // fp16 p rows: 32B (halves 10..15 permanent zeros)
#define NPLANES 4
#define APSTRIDE 16   // fp16 agg plane rows: 32B

__device__ float g_h[(size_t)NNODES * STRIDE];
__device__ __half g_p[(size_t)NNODES * PSTRIDE];
__device__ __half g_aggh[(size_t)NPLANES * NNODES * APSTRIDE];   // 25.6MB

__device__ __forceinline__ float lrelu(float x) { return fmaxf(x, 0.1f * x); }

__device__ __forceinline__ void store_p_fp16(__half* pr, const float* pv) {
    __half2 t0 = __floats2half2_rn(pv[0], pv[1]);
    __half2 t1 = __floats2half2_rn(pv[2], pv[3]);
    __half2 t2 = __floats2half2_rn(pv[4], pv[5]);
    __half2 t3 = __floats2half2_rn(pv[6], pv[7]);
    __half2 t4 = __floats2half2_rn(pv[8], pv[9]);
    uint4 q;
    q.x = *(unsigned*)&t0; q.y = *(unsigned*)&t1;
    q.z = *(unsigned*)&t2; q.w = *(unsigned*)&t3;
    *(uint4*)pr = q;
    uint4 q2;
    q2.x = *(unsigned*)&t4; q2.y = 0u; q2.z = 0u; q2.w = 0u;
    *(uint4*)(pr + 8) = q2;
}

__device__ __forceinline__ void zero_planes(int node) {
    uint4 z = make_uint4(0, 0, 0, 0);
#pragma unroll
    for (int pl = 0; pl < NPLANES; pl++) {
        __half* ar = g_aggh + ((size_t)pl * NNODES + node) * APSTRIDE;
        ((uint4*)ar)[0] = z;
        ((uint4*)ar)[1] = z;
    }
}

// ---------------------------------------------------------------------------
// init: h = lrelu(vertex @ Wi); p = h @ Wg_top; zero agg planes (layer-0 prep)
// float4 row reads with even/odd alignment fixup (row start = node*328B).
// ---------------------------------------------------------------------------
__global__ void init_kernel(const float* __restrict__ vertex,
                            const float* __restrict__ Wi,
                            const float* __restrict__ Wg, int n) {
    __shared__ float wi[AF * H];
    __shared__ float wg[H * H];
    for (int i = threadIdx.x; i < AF * H; i += blockDim.x) wi[i] = Wi[i];
    for (int i = threadIdx.x; i < H * H; i += blockDim.x) wg[i] = Wg[i];
    __syncthreads();
    int node = blockIdx.x * blockDim.x + threadIdx.x;
    if (node >= n) return;

    zero_planes(node);

    const float* row = vertex + (size_t)node * AF;
    float acc[H];
#pragma unroll
    for (int j = 0; j < H; j++) acc[j] = 0.f;

    int base = (node & 1) ? 2 : 0;
    if (node & 1) {
        float2 hd = *(const float2*)row;
#pragma unroll
        for (int j = 0; j < H; j++)
            acc[j] += hd.x * wi[0 * H + j] + hd.y * wi[1 * H + j];
    }
    const float4* r4 = (const float4*)(row + base);
    const float* wb = wi + base * H;
#pragma unroll
    for (int i = 0; i < 20; i++) {
        float4 v = r4[i];
        const float* wk = wb + (4 * i) * H;
#pragma unroll
        for (int j = 0; j < H; j++)
            acc[j] += v.x * wk[j] + v.y * wk[H + j] +
                      v.z * wk[2 * H + j] + v.w * wk[3 * H + j];
    }
    if (!(node & 1)) {
        float2 tl = *(const float2*)(row + 80);
#pragma unroll
        for (int j = 0; j < H; j++)
            acc[j] += tl.x * wi[80 * H + j] + tl.y * wi[81 * H + j];
    }

    float h[H];
#pragma unroll
    for (int j = 0; j < H; j++) h[j] = lrelu(acc[j]);

    float pv[H];
#pragma unroll
    for (int j = 0; j < H; j++) {
        float a = 0.f;
#pragma unroll
        for (int i = 0; i < H; i++) a += h[i] * wg[i * H + j];
        pv[j] = a;
    }

    float4* hw = (float4*)(g_h + (size_t)node * STRIDE);
    hw[0] = make_float4(h[0], h[1], h[2], h[3]);
    hw[1] = make_float4(h[4], h[5], h[6], h[7]);
    hw[2] = make_float4(h[8], h[9], 0.f, 0.f);
    store_p_fp16(g_p + (size_t)node * PSTRIDE, pv);
}

// ---------------------------------------------------------------------------
// edge: 2 lanes per edge (role = tid&1). Each lane: one LDG.128 p-gather of
// its 16B half-row, 8 output dims, one red.v4.f16x2 into its 16B half of the
// agg row (plane = e&3). Proven R7 structure — do not re-stage ef.
// ---------------------------------------------------------------------------
__global__ void __launch_bounds__(256, 8)
edge_kernel(const float* __restrict__ ef,
            const int* __restrict__ src,
            const int* __restrict__ dst,
            const float* __restrict__ Wg, int ecnt) {
    __shared__ float wpad[ED][16];
    for (int i = threadIdx.x; i < ED * 16; i += blockDim.x) {
        int k = i >> 4, j = i & 15;
        wpad[k][j] = (j < H) ? Wg[(H + k) * H + j] : 0.f;
    }
    __syncthreads();

    int tid = blockIdx.x * blockDim.x + threadIdx.x;
    int e = tid >> 1;
    int role = tid & 1;
    if (e >= ecnt) return;

    int s = src[e];
    int d = dst[e];

    const float2* ep = (const float2*)(ef + (size_t)e * ED);
    float2 f0 = ep[0], f1 = ep[1], f2 = ep[2];
    float ev[ED] = {f0.x, f0.y, f1.x, f1.y, f2.x, f2.y};

    const __half* pr = g_p + (size_t)s * PSTRIDE + role * 8;
    uint4 q = *(const uint4*)pr;
    float pl[8];
    {
        float2 f;
        f = __half22float2(*(__half2*)&q.x); pl[0] = f.x; pl[1] = f.y;
        f = __half22float2(*(__half2*)&q.y); pl[2] = f.x; pl[3] = f.y;
        f = __half22float2(*(__half2*)&q.z); pl[4] = f.x; pl[5] = f.y;
        f = __half22float2(*(__half2*)&q.w); pl[6] = f.x; pl[7] = f.y;
    }

    const float* wj = &wpad[0][role * 8];
    float m[8];
#pragma unroll
    for (int jj = 0; jj < 8; jj++) {
        float a = pl[jj];
#pragma unroll
        for (int k = 0; k < ED; k++) a += ev[k] * wj[k * 16 + jj];
        m[jj] = lrelu(a);
    }

    __half2 h0 = __floats2half2_rn(m[0], m[1]);
    __half2 h1 = __floats2half2_rn(m[2], m[3]);
    __half2 h2 = __floats2half2_rn(m[4], m[5]);
    __half2 h3 = __floats2half2_rn(m[6], m[7]);

    int plane = e & (NPLANES - 1);
    __half* ap = g_aggh + ((size_t)plane * NNODES + d) * APSTRIDE + role * 8;
    asm volatile("red.global.add.noftz.v4.f16x2 [%0], {%1,%2,%3,%4};" ::
                 "l"(ap), "r"(*(unsigned*)&h0), "r"(*(unsigned*)&h1),
                 "r"(*(unsigned*)&h2), "r"(*(unsigned*)&h3) : "memory");
}

// ---------------------------------------------------------------------------
// update: agg = sum of 4 fp16 planes; h' = lrelu([h,agg] @ Wu);
// layer 0: also write p' and re-zero planes for next layer
// ---------------------------------------------------------------------------
__global__ void update_kernel(const float* __restrict__ Wu,
                              const float* __restrict__ Wg,
                              float* __restrict__ out, int n,
                              int out_stride, int write_p) {
    __shared__ float wu[2 * H * H];
    __shared__ float wg[H * H];
    for (int i = threadIdx.x; i < 2 * H * H; i += blockDim.x) wu[i] = Wu[i];
    for (int i = threadIdx.x; i < H * H; i += blockDim.x) wg[i] = Wg[i];
    __syncthreads();

    int node = blockIdx.x * blockDim.x + threadIdx.x;
    if (node >= n) return;

    size_t off = (size_t)node * STRIDE;
    const float4* hr = (const float4*)(g_h + off);
    float4 h0 = hr[0], h1 = hr[1], h2 = hr[2];
    float hv[H] = {h0.x, h0.y, h0.z, h0.w, h1.x, h1.y, h1.z, h1.w, h2.x, h2.y};

    float av[H];
#pragma unroll
    for (int j = 0; j < H; j++) av[j] = 0.f;
#pragma unroll
    for (int pl = 0; pl < NPLANES; pl++) {
        const __half* ar = g_aggh + ((size_t)pl * NNODES + node) * APSTRIDE;
        uint4 q = *(const uint4*)ar;
        unsigned t = *(const unsigned*)(ar + 8);
        float2 f;
        f = __half22float2(*(__half2*)&q.x); av[0] += f.x; av[1] += f.y;
        f = __half22float2(*(__half2*)&q.y); av[2] += f.x; av[3] += f.y;
        f = __half22float2(*(__half2*)&q.z); av[4] += f.x; av[5] += f.y;
        f = __half22float2(*(__half2*)&q.w); av[6] += f.x; av[7] += f.y;
        f = __half22float2(*(__half2*)&t);   av[8] += f.x; av[9] += f.y;
    }

    if (write_p) zero_planes(node);   // prep planes for next layer

    float o[H];
#pragma unroll
    for (int j = 0; j < H; j++) {
        float a = 0.f;
#pragma unroll
        for (int i = 0; i < H; i++) a += hv[i] * wu[i * H + j];
#pragma unroll
        for (int i = 0; i < H; i++) a += av[i] * wu[(H + i) * H + j];
        o[j] = lrelu(a);
    }

    if (out_stride == STRIDE) {
        float4* ow = (float4*)(out + (size_t)node * STRIDE);
        ow[0] = make_float4(o[0], o[1], o[2], o[3]);
        ow[1] = make_float4(o[4], o[5], o[6], o[7]);
        ow[2] = make_float4(o[8], o[9], 0.f, 0.f);
    } else {
        float2* ow = (float2*)(out + (size_t)node * H);
#pragma unroll
        for (int j = 0; j < H / 2; j++) ow[j] = make_float2(o[2 * j], o[2 * j + 1]);
    }

    if (write_p) {
        float pv[H];
#pragma unroll
        for (int j = 0; j < H; j++) {
            float a = 0.f;
#pragma unroll
            for (int i = 0; i < H; i++) a += o[i] * wg[i * H + j];
            pv[j] = a;
        }
        store_p_fp16(g_p + (size_t)node * PSTRIDE, pv);
    }
}

// ---------------------------------------------------------------------------
extern "C" void kernel_launch(void* const* d_in, const int* in_sizes, int n_in,
                              void* d_out, int out_size) {
    const float* vertex = (const float*)d_in[0];
    const float* ef = (const float*)d_in[1];
    const int* src = (const int*)d_in[2];
    const int* dst = (const int*)d_in[3];
    const float* Wi = (const float*)d_in[4];
    const float* Wg = (const float*)d_in[5];
    const float* Wu = (const float*)d_in[6];
    float* out = (float*)d_out;

    int n = in_sizes[0] / AF;
    int e = in_sizes[2];

    void* hp = nullptr;
    cudaGetSymbolAddress(&hp, g_h);

    int nb = (n + 255) / 256;
    long long lanes = 2LL * e;
    int eb = (int)((lanes + 255) / 256);

    init_kernel<<<nb, 256>>>(vertex, Wi, Wg, n);
    for (int l = 0; l < 2; l++) {
        edge_kernel<<<eb, 256>>>(ef, src, dst, Wg, e);
        update_kernel<<<nb, 256>>>(Wu, Wg, (l == 1) ? out : (float*)hp, n,
                                   (l == 1) ? H : STRIDE, (l == 0) ? 1 : 0);
    }
}